// round 2
// baseline (speedup 1.0000x reference)
#include <cuda_runtime.h>
#include <cuda_bf16.h>

// Problem constants
#define NN 8192
#define DD 256
#define KK 8
#define CC 1024          // NN / KK classes
#define MARGIN2 0.7f

// Scratch (no allocations allowed)
__device__ float g_centers[CC * DD];   // unnormalized class centers (means of normalized rows)
__device__ float g_sq[CC];             // ||center||^2
__device__ float g_dpc[CC];            // per-class sum of dist_pc over its 8 samples
__device__ float g_an_part[CC * 16];   // per-class, per-column-chunk hinge partial sums

// ---------------------------------------------------------------------------
// Kernel A: per-class centers + dist_pc.  grid = 1024 blocks, 256 threads.
// Warp w handles sample row c*8+w.
// ---------------------------------------------------------------------------
__global__ __launch_bounds__(256) void centers_kernel(const float* __restrict__ x) {
    __shared__ float sh[KK][DD];     // normalized rows
    __shared__ float cent[DD];       // class center
    __shared__ float wsum[KK];
    __shared__ float s_sq;

    const int c    = blockIdx.x;
    const int t    = threadIdx.x;
    const int w    = t >> 5;
    const int lane = t & 31;

    const float* row = x + (size_t)(c * KK + w) * DD;

    float v[8];
    float ss = 0.f;
#pragma unroll
    for (int i = 0; i < 8; i++) {
        v[i] = row[lane + 32 * i];
        ss += v[i] * v[i];
    }
#pragma unroll
    for (int o = 16; o; o >>= 1) ss += __shfl_xor_sync(0xFFFFFFFFu, ss, o);
    const float rn = rsqrtf(ss);
#pragma unroll
    for (int i = 0; i < 8; i++) sh[w][lane + 32 * i] = v[i] * rn;
    __syncthreads();

    // center column t = mean over 8 normalized rows
    float cv = 0.f;
#pragma unroll
    for (int r = 0; r < KK; r++) cv += sh[r][t];
    cv *= 0.125f;
    cent[t] = cv;
    g_centers[c * DD + t] = cv;

    // ||center||^2 : block reduction (deterministic)
    float sq = cv * cv;
#pragma unroll
    for (int o = 16; o; o >>= 1) sq += __shfl_xor_sync(0xFFFFFFFFu, sq, o);
    if (lane == 0) wsum[w] = sq;
    __syncthreads();
    if (t == 0) {
        float s = 0.f;
#pragma unroll
        for (int r = 0; r < KK; r++) s += wsum[r];
        g_sq[c] = s;
        s_sq = s;
    }
    __syncthreads();

    const float rcn = rsqrtf(s_sq);

    // dist_pc for row w: ||x_norm - center_norm||
    float dd = 0.f;
#pragma unroll
    for (int i = 0; i < 8; i++) {
        const int d = lane + 32 * i;
        const float diff = sh[w][d] - cent[d] * rcn;
        dd += diff * diff;
    }
#pragma unroll
    for (int o = 16; o; o >>= 1) dd += __shfl_xor_sync(0xFFFFFFFFu, dd, o);
    if (lane == 0) wsum[w] = sqrtf(dd);       // safe: all reads of wsum done before 2nd barrier above? yes
    __syncthreads();
    if (t == 0) {
        float s = 0.f;
#pragma unroll
        for (int r = 0; r < KK; r++) s += wsum[r];
        g_dpc[c] = s;
    }
}

// ---------------------------------------------------------------------------
// Kernel B: 1024x1024 class-center pairwise hinge.
// Tile: 128 rows x 64 cols, K-chunks of 32.  grid = (16 col-chunks, 8 row-chunks),
// 256 threads, 8x4 register micro-tile per thread.
// ---------------------------------------------------------------------------
#define TR 128
#define TC 64
#define TK 32

__global__ __launch_bounds__(256) void pair_kernel() {
    __shared__ float As[TK][136];   // 136: 16B-aligned rows (vectorized LDS)
    __shared__ float Bs[TK][68];    // 68:  16B-aligned rows
    __shared__ float smr[TR][17];   // row partial sums per tx

    const int rb = blockIdx.y * TR;
    const int cb = blockIdx.x * TC;
    const int t  = threadIdx.x;
    const int tx = t & 15;          // 0..15 -> 4 cols each
    const int ty = t >> 4;          // 0..15 -> 8 rows each

    float acc[8][4];
#pragma unroll
    for (int i = 0; i < 8; i++)
#pragma unroll
        for (int j = 0; j < 4; j++) acc[i][j] = 0.f;

    for (int kt = 0; kt < DD; kt += TK) {
        // load A tile: 128 rows x 32 k (transposed into k-major)
#pragma unroll
        for (int i = 0; i < 16; i++) {
            const int idx = t + 256 * i;
            const int r = idx >> 5, k = idx & 31;
            As[k][r] = g_centers[(rb + r) * DD + kt + k];
        }
        // load B tile: 64 rows x 32 k
#pragma unroll
        for (int i = 0; i < 8; i++) {
            const int idx = t + 256 * i;
            const int r = idx >> 5, k = idx & 31;
            Bs[k][r] = g_centers[(cb + r) * DD + kt + k];
        }
        __syncthreads();

#pragma unroll
        for (int k = 0; k < TK; k++) {
            const float4* Ar = reinterpret_cast<const float4*>(&As[k][ty * 8]);
            const float4 a0 = Ar[0];
            const float4 a1 = Ar[1];
            const float4 b0 = *reinterpret_cast<const float4*>(&Bs[k][tx * 4]);
            const float a[8] = {a0.x, a0.y, a0.z, a0.w, a1.x, a1.y, a1.z, a1.w};
            const float b[4] = {b0.x, b0.y, b0.z, b0.w};
#pragma unroll
            for (int i = 0; i < 8; i++)
#pragma unroll
                for (int j = 0; j < 4; j++) acc[i][j] = fmaf(a[i], b[j], acc[i][j]);
        }
        __syncthreads();
    }

    // hinge + per-row partial sum
    float sqr[8], sqc[4];
#pragma unroll
    for (int i = 0; i < 8; i++) sqr[i] = g_sq[rb + ty * 8 + i];
#pragma unroll
    for (int j = 0; j < 4; j++) sqc[j] = g_sq[cb + tx * 4 + j];

    float rowsum[8];
#pragma unroll
    for (int i = 0; i < 8; i++) rowsum[i] = 0.f;

#pragma unroll
    for (int i = 0; i < 8; i++) {
        const int r = rb + ty * 8 + i;
#pragma unroll
        for (int j = 0; j < 4; j++) {
            const int cc = cb + tx * 4 + j;
            if (r != cc) {
                const float d2 = fmaxf(sqr[i] + sqc[j] - 2.0f * acc[i][j], 1e-12f);
                rowsum[i] += fmaxf(MARGIN2 - sqrtf(d2), 0.0f);
            }
        }
    }
#pragma unroll
    for (int i = 0; i < 8; i++) smr[ty * 8 + i][tx] = rowsum[i];
    __syncthreads();

    if (t < TR) {
        float s = 0.f;
#pragma unroll
        for (int p = 0; p < 16; p++) s += smr[t][p];
        g_an_part[(rb + t) * 16 + blockIdx.x] = s;
    }
}

// ---------------------------------------------------------------------------
// Kernel C: final deterministic reduction. 1 block, 1024 threads.
// ---------------------------------------------------------------------------
__global__ __launch_bounds__(1024) void reduce_kernel(float* __restrict__ out) {
    __shared__ float sd[1024];
    __shared__ float sa[1024];
    const int t = threadIdx.x;

    float d = g_dpc[t];
    float s = 0.f;
#pragma unroll
    for (int p = 0; p < 16; p++) s += g_an_part[t * 16 + p];
    sd[t] = d;
    sa[t] = s;
    __syncthreads();
    for (int o = 512; o; o >>= 1) {
        if (t < o) { sd[t] += sd[t + o]; sa[t] += sa[t + o]; }
        __syncthreads();
    }
    if (t == 0) {
        const float dpc_mean = sd[0] / (float)NN;
        // dist_an[c] = 8 * S_c / 8184 ; mean over 1024 classes
        const float an_mean = sa[0] * (float)KK / ((float)(NN - KK) * (float)CC);
        out[0] = dpc_mean + an_mean;   // loss
        out[1] = dpc_mean;
        out[2] = an_mean;
    }
}

extern "C" void kernel_launch(void* const* d_in, const int* in_sizes, int n_in,
                              void* d_out, int out_size) {
    const float* x = (const float*)d_in[0];
    // d_in[1] = targets (contiguous blocks of K, implied by layout; unused)
    float* out = (float*)d_out;

    centers_kernel<<<CC, 256>>>(x);
    pair_kernel<<<dim3(16, 8), 256>>>();
    reduce_kernel<<<1, 1024>>>(out);
}

// round 3
// speedup vs baseline: 1.6167x; 1.6167x over previous
#include <cuda_runtime.h>
#include <cuda_bf16.h>

// Problem constants
#define NN 8192
#define DD 256
#define KK 8
#define CC 1024          // NN / KK classes
#define MARGIN2 0.7f
#define NTILE 16         // 1024 / 64 tiles per dim
#define NBLK 136         // NTILE*(NTILE+1)/2 upper-triangular tiles

// Scratch (no allocations allowed)
__device__ float g_centers[CC * DD];   // unnormalized class centers (means of normalized rows)
__device__ float g_sq[CC];             // ||center||^2
__device__ float g_dpc[CC];            // per-class sum of dist_pc over its 8 samples
__device__ float g_an_part[NBLK];      // per-block hinge partial sums

// ---------------------------------------------------------------------------
// Kernel A: per-class centers + dist_pc.  grid = 1024 blocks, 256 threads.
// Warp w handles sample row c*8+w.  float4-vectorized loads/stores.
// ---------------------------------------------------------------------------
__global__ __launch_bounds__(256) void centers_kernel(const float* __restrict__ x) {
    __shared__ float sh[KK][DD];     // normalized rows
    __shared__ float cent[DD];       // class center
    __shared__ float wsum[KK];
    __shared__ float s_sq;

    const int c    = blockIdx.x;
    const int t    = threadIdx.x;
    const int w    = t >> 5;
    const int lane = t & 31;

    const float4* row4 = reinterpret_cast<const float4*>(x + (size_t)(c * KK + w) * DD);
    const float4 a = row4[lane];
    const float4 b = row4[lane + 32];

    float ss = a.x * a.x + a.y * a.y + a.z * a.z + a.w * a.w
             + b.x * b.x + b.y * b.y + b.z * b.z + b.w * b.w;
#pragma unroll
    for (int o = 16; o; o >>= 1) ss += __shfl_xor_sync(0xFFFFFFFFu, ss, o);
    const float rn = rsqrtf(ss);

    float4* sh4 = reinterpret_cast<float4*>(sh[w]);
    sh4[lane]      = make_float4(a.x * rn, a.y * rn, a.z * rn, a.w * rn);
    sh4[lane + 32] = make_float4(b.x * rn, b.y * rn, b.z * rn, b.w * rn);
    __syncthreads();

    // center column t = mean over 8 normalized rows
    float cv = 0.f;
#pragma unroll
    for (int r = 0; r < KK; r++) cv += sh[r][t];
    cv *= 0.125f;
    cent[t] = cv;
    g_centers[c * DD + t] = cv;

    // ||center||^2 : block reduction (deterministic)
    float sq = cv * cv;
#pragma unroll
    for (int o = 16; o; o >>= 1) sq += __shfl_xor_sync(0xFFFFFFFFu, sq, o);
    if (lane == 0) wsum[w] = sq;
    __syncthreads();
    if (t == 0) {
        float s = 0.f;
#pragma unroll
        for (int r = 0; r < KK; r++) s += wsum[r];
        g_sq[c] = s;
        s_sq = s;
    }
    __syncthreads();

    const float rcn = rsqrtf(s_sq);

    // dist_pc for row w: ||x_norm - center_norm||
    float dd = 0.f;
#pragma unroll
    for (int i = 0; i < 8; i++) {
        const int d = lane + 32 * i;
        const float diff = sh[w][d] - cent[d] * rcn;
        dd += diff * diff;
    }
#pragma unroll
    for (int o = 16; o; o >>= 1) dd += __shfl_xor_sync(0xFFFFFFFFu, dd, o);
    __syncthreads();                 // wsum reuse: all prior reads complete
    if (lane == 0) wsum[w] = sqrtf(dd);
    __syncthreads();
    if (t == 0) {
        float s = 0.f;
#pragma unroll
        for (int r = 0; r < KK; r++) s += wsum[r];
        g_dpc[c] = s;
    }
}

// ---------------------------------------------------------------------------
// Kernel B: symmetric 1024x1024 class-center pairwise hinge.
// Upper-triangular 64x64 tiles only (136 blocks = one wave on 148 SMs).
// Off-diagonal tiles weighted x2.  256 threads, 4x4 register micro-tile.
// Output: scalar hinge partial per block.
// ---------------------------------------------------------------------------
#define TT 64
#define TK 32

__global__ __launch_bounds__(256) void pair_kernel() {
    __shared__ float As[TK][TT + 4];   // +4 pad keeps float4 alignment, breaks conflicts
    __shared__ float Bs[TK][TT + 4];
    __shared__ float warp_s[8];

    // decode upper-triangular tile index
    int rem = blockIdx.x;
    int bi = 0;
    while (rem >= NTILE - bi) { rem -= NTILE - bi; bi++; }
    const int bj = bi + rem;

    const int rb = bi * TT;
    const int cb = bj * TT;
    const int t  = threadIdx.x;
    const int tx = t & 15;          // 0..15 -> 4 cols each
    const int ty = t >> 4;          // 0..15 -> 4 rows each

    float acc[4][4];
#pragma unroll
    for (int i = 0; i < 4; i++)
#pragma unroll
        for (int j = 0; j < 4; j++) acc[i][j] = 0.f;

    for (int kt = 0; kt < DD; kt += TK) {
        // load tiles: 64 rows x 32 k each, k-major in smem
#pragma unroll
        for (int i = 0; i < 8; i++) {
            const int idx = t + 256 * i;
            const int r = idx >> 5, k = idx & 31;
            As[k][r] = g_centers[(rb + r) * DD + kt + k];
            Bs[k][r] = g_centers[(cb + r) * DD + kt + k];
        }
        __syncthreads();

#pragma unroll
        for (int k = 0; k < TK; k++) {
            const float4 a4 = *reinterpret_cast<const float4*>(&As[k][ty * 4]);
            const float4 b4 = *reinterpret_cast<const float4*>(&Bs[k][tx * 4]);
            const float a[4] = {a4.x, a4.y, a4.z, a4.w};
            const float b[4] = {b4.x, b4.y, b4.z, b4.w};
#pragma unroll
            for (int i = 0; i < 4; i++)
#pragma unroll
                for (int j = 0; j < 4; j++) acc[i][j] = fmaf(a[i], b[j], acc[i][j]);
        }
        __syncthreads();
    }

    // hinge sum for this tile
    float sqr[4], sqc[4];
#pragma unroll
    for (int i = 0; i < 4; i++) sqr[i] = g_sq[rb + ty * 4 + i];
#pragma unroll
    for (int j = 0; j < 4; j++) sqc[j] = g_sq[cb + tx * 4 + j];

    float s = 0.f;
#pragma unroll
    for (int i = 0; i < 4; i++) {
        const int r = rb + ty * 4 + i;
#pragma unroll
        for (int j = 0; j < 4; j++) {
            const int cc = cb + tx * 4 + j;
            if (r != cc) {
                const float d2 = fmaxf(sqr[i] + sqc[j] - 2.0f * acc[i][j], 1e-12f);
                s += fmaxf(MARGIN2 - sqrtf(d2), 0.0f);
            }
        }
    }
    if (bi != bj) s *= 2.0f;        // transposed tile contributes identically

    // deterministic block reduction
#pragma unroll
    for (int o = 16; o; o >>= 1) s += __shfl_xor_sync(0xFFFFFFFFu, s, o);
    if ((t & 31) == 0) warp_s[t >> 5] = s;
    __syncthreads();
    if (t == 0) {
        float tot = 0.f;
#pragma unroll
        for (int wv = 0; wv < 8; wv++) tot += warp_s[wv];
        g_an_part[blockIdx.x] = tot;
    }
}

// ---------------------------------------------------------------------------
// Kernel C: final deterministic reduction. 1 block, 1024 threads.
// ---------------------------------------------------------------------------
__global__ __launch_bounds__(1024) void reduce_kernel(float* __restrict__ out) {
    __shared__ float sd[1024];
    __shared__ float sa[1024];
    const int t = threadIdx.x;

    sd[t] = g_dpc[t];
    sa[t] = (t < NBLK) ? g_an_part[t] : 0.f;
    __syncthreads();
    for (int o = 512; o; o >>= 1) {
        if (t < o) { sd[t] += sd[t + o]; sa[t] += sa[t + o]; }
        __syncthreads();
    }
    if (t == 0) {
        const float dpc_mean = sd[0] / (float)NN;
        // dist_an[c] = 8 * S_c / 8184 ; mean over 1024 classes
        const float an_mean = sa[0] * (float)KK / ((float)(NN - KK) * (float)CC);
        out[0] = dpc_mean + an_mean;   // loss
        out[1] = dpc_mean;
        out[2] = an_mean;
    }
}

extern "C" void kernel_launch(void* const* d_in, const int* in_sizes, int n_in,
                              void* d_out, int out_size) {
    const float* x = (const float*)d_in[0];
    // d_in[1] = targets (contiguous blocks of K, implied by layout; unused)
    float* out = (float*)d_out;

    centers_kernel<<<CC, 256>>>(x);
    pair_kernel<<<NBLK, 256>>>();
    reduce_kernel<<<1, 1024>>>(out);
}

// round 4
// speedup vs baseline: 2.7436x; 1.6970x over previous
#include <cuda_runtime.h>
#include <cuda_bf16.h>
#include <cstdint>

// Problem constants
#define NN 8192
#define DD 256
#define KK 8
#define CC 1024          // NN / KK classes
#define MARGIN2 0.7f
#define NTILE 16         // 1024 / 64 tiles per dim
#define NBLK 136         // NTILE*(NTILE+1)/2 upper-triangular tiles

// Scratch (no allocations allowed)
__device__ __align__(16) __nv_bfloat16 g_cbf[CC * DD];  // bf16 class centers
__device__ float g_sq[CC];             // ||center||^2 (fp32 exact)
__device__ float g_dpc[CC];            // per-class sum of dist_pc
__device__ float g_an_part[NBLK];      // per-block hinge partial sums

__device__ __forceinline__ float dot4(const float4& a, const float4& b) {
    return a.x * b.x + a.y * b.y + a.z * b.z + a.w * b.w;
}
__device__ __forceinline__ float wreduce(float s) {
#pragma unroll
    for (int o = 16; o; o >>= 1) s += __shfl_xor_sync(0xFFFFFFFFu, s, o);
    return s;
}

// ---------------------------------------------------------------------------
// Kernel A: one WARP per class. No smem, no barriers, 16 LDG.128 in flight.
// grid = 128 blocks x 256 threads (8 warps = 8 classes per block).
// ---------------------------------------------------------------------------
__global__ __launch_bounds__(256) void centers_kernel(const float* __restrict__ x) {
    const int lane = threadIdx.x & 31;
    const int c = blockIdx.x * 8 + (threadIdx.x >> 5);

    const float4* p = reinterpret_cast<const float4*>(x + (size_t)c * KK * DD);
    // lane covers fp32 cols [4*lane,4*lane+4) and [4*lane+128, +132) of each row
    float4 v0[KK], v1[KK];
#pragma unroll
    for (int r = 0; r < KK; r++) {
        v0[r] = p[r * 64 + lane];
        v1[r] = p[r * 64 + lane + 32];
    }

    // per-row inverse norms
    float rn[KK];
#pragma unroll
    for (int r = 0; r < KK; r++) {
        float ss = wreduce(dot4(v0[r], v0[r]) + dot4(v1[r], v1[r]));
        rn[r] = rsqrtf(ss);
    }

    // center (mean of normalized rows), lane-local columns
    float4 c0 = make_float4(0.f, 0.f, 0.f, 0.f), c1 = c0;
#pragma unroll
    for (int r = 0; r < KK; r++) {
        c0.x = fmaf(v0[r].x, rn[r], c0.x); c0.y = fmaf(v0[r].y, rn[r], c0.y);
        c0.z = fmaf(v0[r].z, rn[r], c0.z); c0.w = fmaf(v0[r].w, rn[r], c0.w);
        c1.x = fmaf(v1[r].x, rn[r], c1.x); c1.y = fmaf(v1[r].y, rn[r], c1.y);
        c1.z = fmaf(v1[r].z, rn[r], c1.z); c1.w = fmaf(v1[r].w, rn[r], c1.w);
    }
    c0.x *= 0.125f; c0.y *= 0.125f; c0.z *= 0.125f; c0.w *= 0.125f;
    c1.x *= 0.125f; c1.y *= 0.125f; c1.z *= 0.125f; c1.w *= 0.125f;

    // store bf16 centers (8 bf16 per lane, two uint2 stores)
    {
        __nv_bfloat162 p0 = __floats2bfloat162_rn(c0.x, c0.y);
        __nv_bfloat162 p1 = __floats2bfloat162_rn(c0.z, c0.w);
        __nv_bfloat162 p2 = __floats2bfloat162_rn(c1.x, c1.y);
        __nv_bfloat162 p3 = __floats2bfloat162_rn(c1.z, c1.w);
        uint2 u0, u1;
        u0.x = *reinterpret_cast<uint32_t*>(&p0); u0.y = *reinterpret_cast<uint32_t*>(&p1);
        u1.x = *reinterpret_cast<uint32_t*>(&p2); u1.y = *reinterpret_cast<uint32_t*>(&p3);
        *reinterpret_cast<uint2*>(&g_cbf[c * DD + 4 * lane]) = u0;
        *reinterpret_cast<uint2*>(&g_cbf[c * DD + 4 * lane + 128]) = u1;
    }

    // ||center||^2 and normalized center scale
    const float s_sq = wreduce(dot4(c0, c0) + dot4(c1, c1));
    if (lane == 0) g_sq[c] = s_sq;
    const float rcn = rsqrtf(s_sq);

    // dist_pc per row
    float dpc = 0.f;
#pragma unroll
    for (int r = 0; r < KK; r++) {
        float d;
        float t0 = v0[r].x * rn[r] - c0.x * rcn; d  = t0 * t0;
        float t1 = v0[r].y * rn[r] - c0.y * rcn; d += t1 * t1;
        float t2 = v0[r].z * rn[r] - c0.z * rcn; d += t2 * t2;
        float t3 = v0[r].w * rn[r] - c0.w * rcn; d += t3 * t3;
        float t4 = v1[r].x * rn[r] - c1.x * rcn; d += t4 * t4;
        float t5 = v1[r].y * rn[r] - c1.y * rcn; d += t5 * t5;
        float t6 = v1[r].z * rn[r] - c1.z * rcn; d += t6 * t6;
        float t7 = v1[r].w * rn[r] - c1.w * rcn; d += t7 * t7;
        dpc += sqrtf(wreduce(d));
    }
    if (lane == 0) g_dpc[c] = dpc;
}

// ---------------------------------------------------------------------------
// Kernel B: symmetric pairwise hinge via bf16 mma.sync (m16n8k16).
// 64x64 upper-triangular tiles, 136 blocks, 8 warps (4 row x 2 col),
// each warp 16x32 output. Two K-stages of 128 in smem.
// ---------------------------------------------------------------------------
#define BPAD 136   // bf16 row pitch: 272B stride, conflict-free for ldmatrix

__global__ __launch_bounds__(256) void pair_kernel() {
    __shared__ __nv_bfloat16 As[64][BPAD];
    __shared__ __nv_bfloat16 Bs[64][BPAD];
    __shared__ float warp_s[8];

    // decode upper-triangular tile index
    int rem = blockIdx.x, bi = 0;
    while (rem >= NTILE - bi) { rem -= NTILE - bi; bi++; }
    const int bj = bi + rem;
    const int rb = bi * 64, cb = bj * 64;

    const int t = threadIdx.x;
    const int lane = t & 31;
    const int wid = t >> 5;
    const int wr = wid >> 1;   // 0..3 -> 16-row slab
    const int wc = wid & 1;    // 0..1 -> 32-col slab

    float acc[4][4];
#pragma unroll
    for (int i = 0; i < 4; i++)
#pragma unroll
        for (int j = 0; j < 4; j++) acc[i][j] = 0.f;

    const uint4* gC = reinterpret_cast<const uint4*>(g_cbf);  // 8 bf16 / uint4

    for (int ks = 0; ks < DD; ks += 128) {
        // stage 64x128 bf16 tiles (16 uint4 per row)
#pragma unroll
        for (int i = 0; i < 4; i++) {
            const int idx = t + 256 * i;
            const int r = idx >> 4, cu = idx & 15;
            *reinterpret_cast<uint4*>(&As[r][cu * 8]) = gC[((rb + r) * DD + ks) / 8 + cu];
            *reinterpret_cast<uint4*>(&Bs[r][cu * 8]) = gC[((cb + r) * DD + ks) / 8 + cu];
        }
        __syncthreads();

#pragma unroll
        for (int k0 = 0; k0 < 128; k0 += 16) {
            uint32_t a0, a1, a2, a3;
            {
                uint32_t aaddr = (uint32_t)__cvta_generic_to_shared(
                    &As[wr * 16 + (lane & 15)][k0 + ((lane >> 4) << 3)]);
                asm volatile(
                    "ldmatrix.sync.aligned.m8n8.x4.shared.b16 {%0,%1,%2,%3}, [%4];"
                    : "=r"(a0), "=r"(a1), "=r"(a2), "=r"(a3) : "r"(aaddr));
            }
#pragma unroll
            for (int half = 0; half < 2; half++) {
                uint32_t b0, b1, b2, b3;
                uint32_t baddr = (uint32_t)__cvta_generic_to_shared(
                    &Bs[wc * 32 + half * 16 + (lane & 7) + ((lane >> 4) & 1) * 8]
                       [k0 + ((lane >> 3) & 1) * 8]);
                asm volatile(
                    "ldmatrix.sync.aligned.m8n8.x4.shared.b16 {%0,%1,%2,%3}, [%4];"
                    : "=r"(b0), "=r"(b1), "=r"(b2), "=r"(b3) : "r"(baddr));
                float* c0 = acc[half * 2 + 0];
                float* c1 = acc[half * 2 + 1];
                asm volatile(
                    "mma.sync.aligned.m16n8k16.row.col.f32.bf16.bf16.f32 "
                    "{%0,%1,%2,%3}, {%4,%5,%6,%7}, {%8,%9}, {%0,%1,%2,%3};"
                    : "+f"(c0[0]), "+f"(c0[1]), "+f"(c0[2]), "+f"(c0[3])
                    : "r"(a0), "r"(a1), "r"(a2), "r"(a3), "r"(b0), "r"(b1));
                asm volatile(
                    "mma.sync.aligned.m16n8k16.row.col.f32.bf16.bf16.f32 "
                    "{%0,%1,%2,%3}, {%4,%5,%6,%7}, {%8,%9}, {%0,%1,%2,%3};"
                    : "+f"(c1[0]), "+f"(c1[1]), "+f"(c1[2]), "+f"(c1[3])
                    : "r"(a0), "r"(a1), "r"(a2), "r"(a3), "r"(b2), "r"(b3));
            }
        }
        __syncthreads();
    }

    // epilogue: hinge on each acc element
    // acc layout: c[0]=(r0, c0), c[1]=(r0, c0+1), c[2]=(r0+8, c0), c[3]=(r0+8, c0+1)
    const int r0 = rb + wr * 16 + (lane >> 2);
    const int r1 = r0 + 8;
    const float sqr0 = g_sq[r0];
    const float sqr1 = g_sq[r1];

    float s = 0.f;
#pragma unroll
    for (int tile = 0; tile < 4; tile++) {
        const int c0 = cb + wc * 32 + tile * 8 + 2 * (lane & 3);
        const float sc0 = g_sq[c0];
        const float sc1 = g_sq[c0 + 1];
        if (r0 != c0) {
            const float d2 = fmaxf(sqr0 + sc0 - 2.0f * acc[tile][0], 1e-12f);
            s += fmaxf(MARGIN2 - sqrtf(d2), 0.0f);
        }
        if (r0 != c0 + 1) {
            const float d2 = fmaxf(sqr0 + sc1 - 2.0f * acc[tile][1], 1e-12f);
            s += fmaxf(MARGIN2 - sqrtf(d2), 0.0f);
        }
        if (r1 != c0) {
            const float d2 = fmaxf(sqr1 + sc0 - 2.0f * acc[tile][2], 1e-12f);
            s += fmaxf(MARGIN2 - sqrtf(d2), 0.0f);
        }
        if (r1 != c0 + 1) {
            const float d2 = fmaxf(sqr1 + sc1 - 2.0f * acc[tile][3], 1e-12f);
            s += fmaxf(MARGIN2 - sqrtf(d2), 0.0f);
        }
    }
    if (bi != bj) s *= 2.0f;   // mirrored tile contributes identically

    s = wreduce(s);
    if (lane == 0) warp_s[wid] = s;
    __syncthreads();
    if (t == 0) {
        float tot = 0.f;
#pragma unroll
        for (int wv = 0; wv < 8; wv++) tot += warp_s[wv];
        g_an_part[blockIdx.x] = tot;
    }
}

// ---------------------------------------------------------------------------
// Kernel C: final deterministic reduction. 1 block, 1024 threads.
// ---------------------------------------------------------------------------
__global__ __launch_bounds__(1024) void reduce_kernel(float* __restrict__ out) {
    __shared__ float sd[1024];
    __shared__ float sa[1024];
    const int t = threadIdx.x;

    sd[t] = g_dpc[t];
    sa[t] = (t < NBLK) ? g_an_part[t] : 0.f;
    __syncthreads();
    for (int o = 512; o; o >>= 1) {
        if (t < o) { sd[t] += sd[t + o]; sa[t] += sa[t + o]; }
        __syncthreads();
    }
    if (t == 0) {
        const float dpc_mean = sd[0] / (float)NN;
        const float an_mean = sa[0] * (float)KK / ((float)(NN - KK) * (float)CC);
        out[0] = dpc_mean + an_mean;   // loss
        out[1] = dpc_mean;
        out[2] = an_mean;
    }
}

extern "C" void kernel_launch(void* const* d_in, const int* in_sizes, int n_in,
                              void* d_out, int out_size) {
    const float* x = (const float*)d_in[0];
    float* out = (float*)d_out;

    centers_kernel<<<CC / 8, 256>>>(x);
    pair_kernel<<<NBLK, 256>>>();
    reduce_kernel<<<1, 1024>>>(out);
}

// round 5
// speedup vs baseline: 3.2456x; 1.1830x over previous
#include <cuda_runtime.h>
#include <cuda_bf16.h>
#include <cstdint>

// Problem constants
#define NN 8192
#define DD 256
#define KK 8
#define CC 1024          // NN / KK classes
#define MARGIN2 0.7f
#define NTILE 16         // 1024 / 64 tiles per dim
#define NBLK 136         // NTILE*(NTILE+1)/2 upper-triangular tiles

// Scratch (no allocations allowed)
__device__ __align__(16) __nv_bfloat16 g_cbf[CC * DD];  // bf16 class centers
__device__ float g_sq[CC];             // ||center||^2 (fp32 exact)
__device__ float g_dpc[CC];            // per-class sum of dist_pc
__device__ float g_an_part[NBLK];      // per-block hinge partial sums
__device__ unsigned int g_ctr;         // last-block counter (self-resetting)

__device__ __forceinline__ float dot4(const float4& a, const float4& b) {
    return a.x * b.x + a.y * b.y + a.z * b.z + a.w * b.w;
}
__device__ __forceinline__ float wreduce(float s) {
#pragma unroll
    for (int o = 16; o; o >>= 1) s += __shfl_xor_sync(0xFFFFFFFFu, s, o);
    return s;
}
__device__ __forceinline__ float4 f4_fma(const float4& a, float s, const float4& b) {
    return make_float4(fmaf(a.x, s, b.x), fmaf(a.y, s, b.y),
                       fmaf(a.z, s, b.z), fmaf(a.w, s, b.w));
}

// ---------------------------------------------------------------------------
// Kernel A: 4 warps per class, 2 rows per warp.  grid = 512 blocks x 256 thr
// (2 classes per block).  Only 5 shfl-reduces per warp; smem exchange for the
// cross-warp center sum.  ~28 warps/SM co-resident to hide SHFL/LDG latency.
// ---------------------------------------------------------------------------
__global__ __launch_bounds__(256) void centers_kernel(const float* __restrict__ x) {
    __shared__ float4 sm_part[2][4][64];   // [class][warp][lane f4]
    __shared__ float  sm_dpc[2][4];

    const int t    = threadIdx.x;
    const int lane = t & 31;
    const int wid  = t >> 5;
    const int cls  = wid >> 2;     // class within block
    const int wic  = wid & 3;      // warp within class
    const int c    = blockIdx.x * 2 + cls;

    const float4* p = reinterpret_cast<const float4*>(x + (size_t)c * KK * DD);

    // load 2 rows: lane covers cols [4l,4l+4) and [128+4l, 128+4l+4)
    float4 v[2][2];
#pragma unroll
    for (int r = 0; r < 2; r++) {
        const float4* rp = p + (2 * wic + r) * 64;
        v[r][0] = rp[lane];
        v[r][1] = rp[lane + 32];
    }

    // per-row inverse norms (2 warp reduces)
    float rn[2];
#pragma unroll
    for (int r = 0; r < 2; r++)
        rn[r] = rsqrtf(wreduce(dot4(v[r][0], v[r][0]) + dot4(v[r][1], v[r][1])));

    // partial center sum of this warp's 2 normalized rows
    float4 z = make_float4(0.f, 0.f, 0.f, 0.f);
    float4 ps0 = f4_fma(v[1][0], rn[1], f4_fma(v[0][0], rn[0], z));
    float4 ps1 = f4_fma(v[1][1], rn[1], f4_fma(v[0][1], rn[0], z));
    sm_part[cls][wic][lane]      = ps0;
    sm_part[cls][wic][lane + 32] = ps1;
    __syncthreads();

    // full center (each warp of the class computes identical lane-local copy)
    float4 c0 = sm_part[cls][0][lane];
    float4 c1 = sm_part[cls][0][lane + 32];
#pragma unroll
    for (int w = 1; w < 4; w++) {
        const float4 q0 = sm_part[cls][w][lane];
        const float4 q1 = sm_part[cls][w][lane + 32];
        c0.x += q0.x; c0.y += q0.y; c0.z += q0.z; c0.w += q0.w;
        c1.x += q1.x; c1.y += q1.y; c1.z += q1.z; c1.w += q1.w;
    }
    c0.x *= 0.125f; c0.y *= 0.125f; c0.z *= 0.125f; c0.w *= 0.125f;
    c1.x *= 0.125f; c1.y *= 0.125f; c1.z *= 0.125f; c1.w *= 0.125f;

    // bf16 center store (one warp per class)
    if (wic == 0) {
        __nv_bfloat162 p0 = __floats2bfloat162_rn(c0.x, c0.y);
        __nv_bfloat162 p1 = __floats2bfloat162_rn(c0.z, c0.w);
        __nv_bfloat162 p2 = __floats2bfloat162_rn(c1.x, c1.y);
        __nv_bfloat162 p3 = __floats2bfloat162_rn(c1.z, c1.w);
        uint2 u0, u1;
        u0.x = *reinterpret_cast<uint32_t*>(&p0); u0.y = *reinterpret_cast<uint32_t*>(&p1);
        u1.x = *reinterpret_cast<uint32_t*>(&p2); u1.y = *reinterpret_cast<uint32_t*>(&p3);
        *reinterpret_cast<uint2*>(&g_cbf[c * DD + 4 * lane]) = u0;
        *reinterpret_cast<uint2*>(&g_cbf[c * DD + 4 * lane + 128]) = u1;
    }

    // ||center||^2 (3rd reduce; redundant per warp but latency-cheap)
    const float s_sq = wreduce(dot4(c0, c0) + dot4(c1, c1));
    if (wic == 0 && lane == 0) g_sq[c] = s_sq;
    const float rcn = rsqrtf(s_sq);

    // dist_pc for this warp's 2 rows (reduces 4,5)
    float dpc = 0.f;
#pragma unroll
    for (int r = 0; r < 2; r++) {
        float d;
        float t0 = fmaf(v[r][0].x, rn[r], -c0.x * rcn); d  = t0 * t0;
        float t1 = fmaf(v[r][0].y, rn[r], -c0.y * rcn); d += t1 * t1;
        float t2 = fmaf(v[r][0].z, rn[r], -c0.z * rcn); d += t2 * t2;
        float t3 = fmaf(v[r][0].w, rn[r], -c0.w * rcn); d += t3 * t3;
        float t4 = fmaf(v[r][1].x, rn[r], -c1.x * rcn); d += t4 * t4;
        float t5 = fmaf(v[r][1].y, rn[r], -c1.y * rcn); d += t5 * t5;
        float t6 = fmaf(v[r][1].z, rn[r], -c1.z * rcn); d += t6 * t6;
        float t7 = fmaf(v[r][1].w, rn[r], -c1.w * rcn); d += t7 * t7;
        dpc += sqrtf(wreduce(d));
    }
    if (lane == 0) sm_dpc[cls][wic] = dpc;
    __syncthreads();
    if (wic == 0 && lane == 0)
        g_dpc[c] = (sm_dpc[cls][0] + sm_dpc[cls][1]) + (sm_dpc[cls][2] + sm_dpc[cls][3]);
}

// ---------------------------------------------------------------------------
// Kernel B: symmetric pairwise hinge via bf16 mma.sync (m16n8k16).
// 64x64 upper-triangular tiles, 136 blocks (one wave), 8 warps (4 row x 2 col).
// Last-arriving block performs the final global reduction (no 3rd kernel).
// ---------------------------------------------------------------------------
#define BPAD 136   // bf16 row pitch: 272B stride, conflict-free for ldmatrix

__global__ __launch_bounds__(256) void pair_kernel(float* __restrict__ out) {
    __shared__ __nv_bfloat16 As[64][BPAD];
    __shared__ __nv_bfloat16 Bs[64][BPAD];
    __shared__ float warp_s[8];
    __shared__ unsigned int s_last;

    // decode upper-triangular tile index
    int rem = blockIdx.x, bi = 0;
    while (rem >= NTILE - bi) { rem -= NTILE - bi; bi++; }
    const int bj = bi + rem;
    const int rb = bi * 64, cb = bj * 64;

    const int t = threadIdx.x;
    const int lane = t & 31;
    const int wid = t >> 5;
    const int wr = wid >> 1;   // 0..3 -> 16-row slab
    const int wc = wid & 1;    // 0..1 -> 32-col slab

    float acc[4][4];
#pragma unroll
    for (int i = 0; i < 4; i++)
#pragma unroll
        for (int j = 0; j < 4; j++) acc[i][j] = 0.f;

    const uint4* gC = reinterpret_cast<const uint4*>(g_cbf);  // 8 bf16 / uint4

    for (int ks = 0; ks < DD; ks += 128) {
        // stage 64x128 bf16 tiles (16 uint4 per row)
#pragma unroll
        for (int i = 0; i < 4; i++) {
            const int idx = t + 256 * i;
            const int r = idx >> 4, cu = idx & 15;
            *reinterpret_cast<uint4*>(&As[r][cu * 8]) = gC[((rb + r) * DD + ks) / 8 + cu];
            *reinterpret_cast<uint4*>(&Bs[r][cu * 8]) = gC[((cb + r) * DD + ks) / 8 + cu];
        }
        __syncthreads();

#pragma unroll
        for (int k0 = 0; k0 < 128; k0 += 16) {
            uint32_t a0, a1, a2, a3;
            {
                uint32_t aaddr = (uint32_t)__cvta_generic_to_shared(
                    &As[wr * 16 + (lane & 15)][k0 + ((lane >> 4) << 3)]);
                asm volatile(
                    "ldmatrix.sync.aligned.m8n8.x4.shared.b16 {%0,%1,%2,%3}, [%4];"
                    : "=r"(a0), "=r"(a1), "=r"(a2), "=r"(a3) : "r"(aaddr));
            }
#pragma unroll
            for (int half = 0; half < 2; half++) {
                uint32_t b0, b1, b2, b3;
                uint32_t baddr = (uint32_t)__cvta_generic_to_shared(
                    &Bs[wc * 32 + half * 16 + (lane & 7) + ((lane >> 4) & 1) * 8]
                       [k0 + ((lane >> 3) & 1) * 8]);
                asm volatile(
                    "ldmatrix.sync.aligned.m8n8.x4.shared.b16 {%0,%1,%2,%3}, [%4];"
                    : "=r"(b0), "=r"(b1), "=r"(b2), "=r"(b3) : "r"(baddr));
                float* c0 = acc[half * 2 + 0];
                float* c1 = acc[half * 2 + 1];
                asm volatile(
                    "mma.sync.aligned.m16n8k16.row.col.f32.bf16.bf16.f32 "
                    "{%0,%1,%2,%3}, {%4,%5,%6,%7}, {%8,%9}, {%0,%1,%2,%3};"
                    : "+f"(c0[0]), "+f"(c0[1]), "+f"(c0[2]), "+f"(c0[3])
                    : "r"(a0), "r"(a1), "r"(a2), "r"(a3), "r"(b0), "r"(b1));
                asm volatile(
                    "mma.sync.aligned.m16n8k16.row.col.f32.bf16.bf16.f32 "
                    "{%0,%1,%2,%3}, {%4,%5,%6,%7}, {%8,%9}, {%0,%1,%2,%3};"
                    : "+f"(c1[0]), "+f"(c1[1]), "+f"(c1[2]), "+f"(c1[3])
                    : "r"(a0), "r"(a1), "r"(a2), "r"(a3), "r"(b2), "r"(b3));
            }
        }
        __syncthreads();
    }

    // epilogue: hinge on each acc element
    // acc[tile][0]=(r0,c0)  [1]=(r0,c0+1)  [2]=(r0+8,c0)  [3]=(r0+8,c0+1)
    const int r0 = rb + wr * 16 + (lane >> 2);
    const int r1 = r0 + 8;
    const float sqr0 = g_sq[r0];
    const float sqr1 = g_sq[r1];

    float s = 0.f;
#pragma unroll
    for (int tile = 0; tile < 4; tile++) {
        const int c0 = cb + wc * 32 + tile * 8 + 2 * (lane & 3);
        const float sc0 = g_sq[c0];
        const float sc1 = g_sq[c0 + 1];
        if (r0 != c0) {
            const float d2 = fmaxf(sqr0 + sc0 - 2.0f * acc[tile][0], 1e-12f);
            s += fmaxf(MARGIN2 - sqrtf(d2), 0.0f);
        }
        if (r0 != c0 + 1) {
            const float d2 = fmaxf(sqr0 + sc1 - 2.0f * acc[tile][1], 1e-12f);
            s += fmaxf(MARGIN2 - sqrtf(d2), 0.0f);
        }
        if (r1 != c0) {
            const float d2 = fmaxf(sqr1 + sc0 - 2.0f * acc[tile][2], 1e-12f);
            s += fmaxf(MARGIN2 - sqrtf(d2), 0.0f);
        }
        if (r1 != c0 + 1) {
            const float d2 = fmaxf(sqr1 + sc1 - 2.0f * acc[tile][3], 1e-12f);
            s += fmaxf(MARGIN2 - sqrtf(d2), 0.0f);
        }
    }
    if (bi != bj) s *= 2.0f;   // mirrored tile contributes identically

    s = wreduce(s);
    if (lane == 0) warp_s[wid] = s;
    __syncthreads();
    if (t == 0) {
        float tot = 0.f;
#pragma unroll
        for (int wv = 0; wv < 8; wv++) tot += warp_s[wv];
        g_an_part[blockIdx.x] = tot;
        __threadfence();
        s_last = (atomicAdd(&g_ctr, 1u) == NBLK - 1) ? 1u : 0u;
    }
    __syncthreads();

    // ---- last-arriving block: final deterministic reduction ----
    if (s_last) {
        __shared__ float sdw[8], saw[8];
        // 1024 dpc entries: 4 per thread; 136 an partials: 1 per thread (t<136)
        float d = __ldcg(&g_dpc[t]) + __ldcg(&g_dpc[t + 256])
                + __ldcg(&g_dpc[t + 512]) + __ldcg(&g_dpc[t + 768]);
        float a = (t < NBLK) ? __ldcg(&g_an_part[t]) : 0.f;
        d = wreduce(d);
        a = wreduce(a);
        if (lane == 0) { sdw[wid] = d; saw[wid] = a; }
        __syncthreads();
        if (t == 0) {
            float D = 0.f, A = 0.f;
#pragma unroll
            for (int i = 0; i < 8; i++) { D += sdw[i]; A += saw[i]; }
            const float dpc_mean = D / (float)NN;
            const float an_mean  = A * (float)KK / ((float)(NN - KK) * (float)CC);
            out[0] = dpc_mean + an_mean;   // loss
            out[1] = dpc_mean;
            out[2] = an_mean;
            g_ctr = 0u;                    // reset for next graph replay
        }
    }
}

extern "C" void kernel_launch(void* const* d_in, const int* in_sizes, int n_in,
                              void* d_out, int out_size) {
    const float* x = (const float*)d_in[0];
    float* out = (float*)d_out;

    centers_kernel<<<CC / 2, 256>>>(x);
    pair_kernel<<<NBLK, 256>>>(out);
}